// round 6
// baseline (speedup 1.0000x reference)
#include <cuda_runtime.h>
#include <cstdint>

typedef unsigned long long u64;

#define N_INP   64
#define N_HID   512
#define BATCH   128
#define SEQ     1024
#define DT_C    0.042f
#define CSZ     8
#define BC      8
#define HS      64
#define THREADS 512
#define HYF_P   516     // hy_full row pitch (floats): bank-staggered, 16B-aligned
#define HYD_P   20      // hyD row pitch (floats): 80B -> conflict-free k-consecutive stores

struct __align__(16) Smem {
    float4 W[512 * 16];           // 131072 B  h2h[:,slice], slot = g ^ (k&15)
    float  hyD[512 * HYD_P];      //  40960 B  (k) -> [b0,b0,b1,b1,...,b7,b7]
    float  hy_full[BC * HYF_P];   //  16512 B  all-gathered hy, [b][k]
    float  wrecv[CSZ * BC * HS];  //  16384 B  [src][b][kin]
    float4 scratch[8 * 8 * 16];   //  16384 B  pass1 partials [ks][b][g]
    float4 rec4[BC * 16];         //   2048 B  rec[b][h-slice]
    float  i2h[BC * HS];          //   2048 B
    float  hy_s[BC * HS];         //   2048 B
    float  hz_s[BC * HS];         //   2048 B
    float  biasS[HS], gammaS[HS], epsS[HS];   // 768 B
};                                 // total 230272 B < 232448 limit

__device__ __forceinline__ uint32_t smem_u32(const void* p) {
    uint32_t a;
    asm("{ .reg .u64 t; cvta.to.shared.u64 t, %1; cvt.u32.u64 %0, t; }"
        : "=r"(a) : "l"(p));
    return a;
}
__device__ __forceinline__ uint32_t mapa_u32(uint32_t a, uint32_t r) {
    uint32_t d;
    asm("mapa.shared::cluster.u32 %0, %1, %2;" : "=r"(d) : "r"(a), "r"(r));
    return d;
}
__device__ __forceinline__ void st_cluster_f32(uint32_t a, float v) {
    asm volatile("st.shared::cluster.f32 [%0], %1;" :: "r"(a), "f"(v) : "memory");
}
__device__ __forceinline__ uint32_t ctarank() {
    uint32_t r;
    asm("mov.u32 %0, %%cluster_ctarank;" : "=r"(r));
    return r;
}
__device__ __forceinline__ void fma2(u64& d, u64 a, u64 b) {
    asm("fma.rn.f32x2 %0, %1, %2, %0;" : "+l"(d) : "l"(a), "l"(b));
}
__device__ __forceinline__ float2 unpk(u64 v) {
    float2 f;
    asm("mov.b64 {%0, %1}, %2;" : "=f"(f.x), "=f"(f.y) : "l"(v));
    return f;
}
__device__ __forceinline__ u64 dup_f32(float v) {
    u64 d;
    asm("mov.b64 %0, {%1, %1};" : "=l"(d) : "f"(v));
    return d;
}
// tanh(x) = 1 - 2/(e^{2x}+1); e^{2x} = 2^{x*2/ln2}.  ~1e-6 rel err, 2 MUFU.
__device__ __forceinline__ float ftanh(float x) {
    float e, r;
    asm("ex2.approx.f32 %0, %1;" : "=f"(e) : "f"(x * 2.885390082f));
    asm("rcp.approx.f32 %0, %1;" : "=f"(r) : "f"(e + 1.0f));
    return fmaf(-2.0f, r, 1.0f);
}
#define CLUSTER_ARRIVE() asm volatile("barrier.cluster.arrive.aligned;" ::: "memory")
#define CLUSTER_WAIT()   asm volatile("barrier.cluster.wait.aligned;" ::: "memory")
#define CLUSTER_SYNC()   do { CLUSTER_ARRIVE(); CLUSTER_WAIT(); } while (0)

// ===================== prelude: i2h_all = tanh(x @ x2h) -> out ==============
#define PRE_CTAS 512
#define XDP 130     // xd dup-row pitch (floats): conflict-free across rq
__global__ void __launch_bounds__(512, 1)
i2h_kernel(const float* __restrict__ x, const float* __restrict__ x2h,
           float* __restrict__ out)
{
    extern __shared__ float ps[];
    float* W2 = ps;                    // 64*512 floats
    float* xd = ps + 64 * 512;         // 16 dup-rows * XDP
    const int t = threadIdx.x;

    for (int idx = t; idx < 64 * 512 / 4; idx += 512)
        *reinterpret_cast<float4*>(&W2[idx * 4]) =
            *reinterpret_cast<const float4*>(&x2h[idx * 4]);

    const int hg = t >> 3;      // 0..63: 8-wide h group
    const int rq = t & 7;       // 0..7: row pair within 16-row tile
    const long r0 = (long)blockIdx.x * 256;

    for (int tile = 0; tile < 16; ++tile) {
        __syncthreads();
        #pragma unroll
        for (int rr = 0; rr < 2; ++rr) {
            int e = t + rr * 512;              // 0..1023
            int row = e >> 6, i = e & 63;
            float v = x[(r0 + tile * 16 + row) * 64 + i];
            *reinterpret_cast<float2*>(&xd[row * XDP + i * 2]) = make_float2(v, v);
        }
        __syncthreads();

        u64 acc[2][4];
        #pragma unroll
        for (int a = 0; a < 2; ++a)
            #pragma unroll
            for (int b = 0; b < 4; ++b) acc[a][b] = 0ull;

        const float* xe_p = &xd[(rq * 2 + 0) * XDP];
        const float* xo_p = &xd[(rq * 2 + 1) * XDP];
        #pragma unroll 8
        for (int i = 0; i < 64; ++i) {
            ulonglong2 wA = *reinterpret_cast<const ulonglong2*>(&W2[i * 512 + hg * 8]);
            ulonglong2 wB = *reinterpret_cast<const ulonglong2*>(&W2[i * 512 + hg * 8 + 4]);
            u64 xe = *reinterpret_cast<const u64*>(&xe_p[i * 2]);
            u64 xo = *reinterpret_cast<const u64*>(&xo_p[i * 2]);
            fma2(acc[0][0], wA.x, xe); fma2(acc[0][1], wA.y, xe);
            fma2(acc[0][2], wB.x, xe); fma2(acc[0][3], wB.y, xe);
            fma2(acc[1][0], wA.x, xo); fma2(acc[1][1], wA.y, xo);
            fma2(acc[1][2], wB.x, xo); fma2(acc[1][3], wB.y, xo);
        }
        #pragma unroll
        for (int rr = 0; rr < 2; ++rr) {
            long row = r0 + tile * 16 + rq * 2 + rr;
            float4 o0, o1; float2 f;
            f = unpk(acc[rr][0]); o0.x = ftanh(f.x); o0.y = ftanh(f.y);
            f = unpk(acc[rr][1]); o0.z = ftanh(f.x); o0.w = ftanh(f.y);
            f = unpk(acc[rr][2]); o1.x = ftanh(f.x); o1.y = ftanh(f.y);
            f = unpk(acc[rr][3]); o1.z = ftanh(f.x); o1.w = ftanh(f.y);
            *reinterpret_cast<float4*>(&out[row * 512 + hg * 8])     = o0;
            *reinterpret_cast<float4*>(&out[row * 512 + hg * 8 + 4]) = o1;
        }
    }
}

// ===================== main recurrence =====================================
__global__ void __launch_bounds__(THREADS, 1) __cluster_dims__(CSZ, 1, 1)
piron_kernel(const float* __restrict__ h2h,
             const float* __restrict__ bias,
             const float* __restrict__ gamma,
             const float* __restrict__ eps,
             float* outp,
             int out_size)
{
    extern __shared__ Smem smem[];
    Smem& S = smem[0];
    const int      t       = threadIdx.x;
    const uint32_t rank    = ctarank();
    const int      cluster = blockIdx.x / CSZ;
    const int      h0      = (int)rank * HS;

    // ---- init ----
    for (int idx = t; idx < 512 * 16; idx += THREADS) {
        int k = idx >> 4, gq = idx & 15;
        float4 v = *reinterpret_cast<const float4*>(h2h + (size_t)k * N_HID + h0 + gq * 4);
        S.W[(k << 4) | (gq ^ (k & 15))] = v;
    }
    if (t < HS) {
        S.biasS[t]  = bias[h0 + t];
        S.gammaS[t] = gamma[h0 + t];
        S.epsS[t]   = eps[h0 + t];
    }
    { S.hy_s[t] = 0.f; S.hz_s[t] = 0.f; }
    for (int idx = t; idx < BC * HYF_P; idx += THREADS) S.hy_full[idx] = 0.f;
    __syncthreads();
    CLUSTER_SYNC();

    // ---- thread roles ----
    // pass1: warp = (ks, gh); lane = bp*8 + g8
    const int ks = t >> 6;                 // 0..7 k-split (64 k each)
    const int gh = (t >> 5) & 1;           // g half
    const int bp = (t >> 3) & 3;           // batch pair
    const int g  = gh * 8 + (t & 7);       // 0..15 h-quad
    // pass2: k = t. update/E: b = t>>6, kk = t&63 (t = b*64+kk)
    const int eb = t >> 6;
    const int ekk = t & 63;

    // precomputed DSMEM addresses
    uint32_t wr_addr[8];
    {
        uint32_t peer = (uint32_t)(t >> 6);
        int kin = t & 63;
        #pragma unroll
        for (int b = 0; b < 8; ++b)
            wr_addr[b] = mapa_u32(
                smem_u32(&S.wrecv[(int)rank * 512 + b * 64 + kin]), peer);
    }
    uint32_t hyb_addr[CSZ];
    {
        uint32_t loc = smem_u32(&S.hy_full[eb * HYF_P + h0 + ekk]);
        #pragma unroll
        for (uint32_t p = 0; p < CSZ; ++p) hyb_addr[p] = mapa_u32(loc, p);
    }

    float* recF = reinterpret_cast<float*>(S.rec4);
    const float* scF = reinterpret_cast<const float*>(S.scratch);

    for (int step = 0; step < SEQ; ++step) {
        // ---- A: hy_full -> hyD (transpose + dup), thread per k ----
        {
            u64 d[8];
            #pragma unroll
            for (int b = 0; b < 8; ++b)
                d[b] = dup_f32(S.hy_full[b * HYF_P + t]);
            ulonglong2* dst = reinterpret_cast<ulonglong2*>(&S.hyD[t * HYD_P]);
            ulonglong2 m;
            m.x = d[0]; m.y = d[1]; dst[0] = m;
            m.x = d[2]; m.y = d[3]; dst[1] = m;
            m.x = d[4]; m.y = d[5]; dst[2] = m;
            m.x = d[6]; m.y = d[7]; dst[3] = m;
        }
        __syncthreads();

        // ---- B: pass1 partials + i2h prefetch ----
        float4 i2v;
        if (t < 128)
            i2v = *reinterpret_cast<const float4*>(
                outp + (((size_t)(cluster * BC + (t >> 4))) * SEQ + step) * N_HID
                     + h0 + (t & 15) * 4);
        {
            const float4* Wp = S.W + (ks << 10);
            const float*  Hp = S.hyD + ks * 64 * HYD_P + bp * 4;
            u64 a00 = 0, a01 = 0, a10 = 0, a11 = 0;
            #pragma unroll 16
            for (int j = 0; j < 64; ++j) {
                ulonglong2 w2 = *reinterpret_cast<const ulonglong2*>(
                    Wp + (j << 4) + (g ^ (j & 15)));
                ulonglong2 h2 = *reinterpret_cast<const ulonglong2*>(Hp + j * HYD_P);
                fma2(a00, w2.x, h2.x); fma2(a01, w2.y, h2.x);
                fma2(a10, w2.x, h2.y); fma2(a11, w2.y, h2.y);
            }
            ulonglong2 s;
            s.x = a00; s.y = a01;
            *reinterpret_cast<ulonglong2*>(&S.scratch[(ks * 8 + bp * 2 + 0) * 16 + g]) = s;
            s.x = a10; s.y = a11;
            *reinterpret_cast<ulonglong2*>(&S.scratch[(ks * 8 + bp * 2 + 1) * 16 + g]) = s;
        }
        if (t < 128)
            *reinterpret_cast<float4*>(&S.i2h[(t >> 4) * 64 + (t & 15) * 4]) = i2v;
        __syncthreads();

        // ---- C: reduce 8 splits + bias + tanh -> recF (1 elem/thread) ----
        {
            float v = S.biasS[ekk];
            #pragma unroll
            for (int s = 0; s < 8; ++s) v += scF[(s * 8 + eb) * 64 + ekk];
            recF[t] = ftanh(v);
        }
        __syncthreads();

        // ---- D: pass2, thread per k: w[b][k] = sum_h rec[b][h]*W[k][h] ----
        {
            const float4* Wr = S.W + (t << 4);
            const int swz = t & 15;
            u64 acc[8];
            #pragma unroll
            for (int b = 0; b < 8; ++b) acc[b] = 0ull;
            #pragma unroll
            for (int gg = 0; gg < 16; ++gg) {
                ulonglong2 w2 = *reinterpret_cast<const ulonglong2*>(Wr + (gg ^ swz));
                #pragma unroll
                for (int b = 0; b < 8; ++b) {
                    ulonglong2 r2 = *reinterpret_cast<const ulonglong2*>(
                        &recF[b * 64 + gg * 4]);
                    fma2(acc[b], w2.x, r2.x);
                    fma2(acc[b], w2.y, r2.y);
                }
            }
            #pragma unroll
            for (int b = 0; b < 8; ++b) {
                float2 f = unpk(acc[b]);
                st_cluster_f32(wr_addr[b], f.x + f.y);
            }
        }
        CLUSTER_ARRIVE();                 // sync1: release scatter

        // preload local update operands while peers drain
        float hy = S.hy_s[t];
        float hz = S.hz_s[t];
        float i2 = S.i2h[t];
        float gm = S.gammaS[ekk];
        float ep = S.epsS[ekk];
        CLUSTER_WAIT();

        // ---- E: reduce wrecv, update, emit, all-gather hy ----
        {
            float w = 0.f;
            #pragma unroll
            for (int src = 0; src < 8; ++src) w += S.wrecv[src * 512 + t];
            hz += DT_C * (i2 - w - gm * hy - ep * hz);
            hy += DT_C * hz;
            S.hy_s[t] = hy;
            S.hz_s[t] = hz;
            outp[(((size_t)(cluster * BC + eb)) * SEQ + step) * N_HID + h0 + ekk] = hy;
            #pragma unroll
            for (uint32_t p = 0; p < CSZ; ++p) st_cluster_f32(hyb_addr[p], hy);
        }
        CLUSTER_SYNC();                   // sync2: hy_full consistent
    }

    // ---- final hy appended after states ----
    if (out_size >= BATCH * SEQ * N_HID + BATCH * N_HID) {
        outp[(size_t)BATCH * SEQ * N_HID +
             (size_t)(cluster * BC + eb) * N_HID + h0 + ekk] = S.hy_s[t];
    }
}

extern "C" void kernel_launch(void* const* d_in, const int* in_sizes, int n_in,
                              void* d_out, int out_size) {
    (void)in_sizes; (void)n_in;
    const float* x     = (const float*)d_in[0];
    const float* x2h   = (const float*)d_in[1];
    const float* h2h   = (const float*)d_in[2];
    const float* bias  = (const float*)d_in[3];
    const float* gamma = (const float*)d_in[4];
    const float* eps   = (const float*)d_in[5];
    float* out = (float*)d_out;

    const int pre_smem = (64 * 512 + 16 * XDP) * 4;
    cudaFuncSetAttribute(i2h_kernel,
                         cudaFuncAttributeMaxDynamicSharedMemorySize, pre_smem);
    cudaFuncSetAttribute(piron_kernel,
                         cudaFuncAttributeMaxDynamicSharedMemorySize, (int)sizeof(Smem));

    i2h_kernel<<<PRE_CTAS, 512, pre_smem>>>(x, x2h, out);
    piron_kernel<<<(BATCH / BC) * CSZ, THREADS, sizeof(Smem)>>>(
        h2h, bias, gamma, eps, out, out_size);
}